// round 2
// baseline (speedup 1.0000x reference)
#include <cuda_runtime.h>

#define V 6
#define U 4
#define STEPS 63   // 64th step's output is discarded by the reference

__device__ float g_vels[8];

__device__ __forceinline__ float fast_sigmoid(float x) {
    return __fdividef(1.0f, 1.0f + __expf(-x));
}

__device__ __forceinline__ float fast_tanh(float x) {
    return 1.0f - __fdividef(2.0f, __expf(2.0f * x) + 1.0f);
}

// One thread per j (V=6 active lanes). Each j-chain is fully independent:
// gates[j,u] use only x[j] and h[j,:]; out[j] uses only h[j,:]. No shuffles.
__global__ void recurrence_kernel(
    const float* __restrict__ vel,
    const float* __restrict__ Wix, const float* __restrict__ Wih, const float* __restrict__ bi,
    const float* __restrict__ Wfx, const float* __restrict__ Wfh, const float* __restrict__ bf,
    const float* __restrict__ Wox, const float* __restrict__ Woh, const float* __restrict__ bo,
    const float* __restrict__ Wgx, const float* __restrict__ Wgh, const float* __restrict__ bg,
    const float* __restrict__ linear, const float* __restrict__ bl,
    const float* __restrict__ h0, const float* __restrict__ c0)
{
    int j = threadIdx.x;
    if (j >= V) return;

    // Per-j weights into registers (~100 regs; single block, so fine)
    float wix[U], wfx[U], wox[U], wgx[U];
    float bii[U], bff[U], boo[U], bgg[U];
    float wih[U][U], wfh[U][U], woh[U][U], wgh[U][U];
    float lin[U];
    float h[U], c[U];

#pragma unroll
    for (int u = 0; u < U; ++u) {
        int t = j * U + u;
        wix[u] = Wix[t]; wfx[u] = Wfx[t]; wox[u] = Wox[t]; wgx[u] = Wgx[t];
        bii[u] = bi[t];  bff[u] = bf[t];  boo[u] = bo[t];  bgg[u] = bg[t];
        lin[u] = linear[t];
        h[u] = h0[t]; c[u] = c0[t];
#pragma unroll
        for (int k = 0; k < U; ++k) {
            wih[u][k] = Wih[t * U + k];
            wfh[u][k] = Wfh[t * U + k];
            woh[u][k] = Woh[t * U + k];
            wgh[u][k] = Wgh[t * U + k];
        }
    }
    float blj = bl[j];
    float x = vel[j];
    float vacc = 0.0f;

#pragma unroll 1
    for (int s = 0; s < STEPS; ++s) {
        float pi[U], pf[U], po[U], pg[U];
#pragma unroll
        for (int u = 0; u < U; ++u) {
            float a = fmaf(wix[u], x, bii[u]);
            float b = fmaf(wfx[u], x, bff[u]);
            float d = fmaf(wox[u], x, boo[u]);
            float e = fmaf(wgx[u], x, bgg[u]);
#pragma unroll
            for (int k = 0; k < U; ++k) {
                a = fmaf(wih[u][k], h[k], a);
                b = fmaf(wfh[u][k], h[k], b);
                d = fmaf(woh[u][k], h[k], d);
                e = fmaf(wgh[u][k], h[k], e);
            }
            pi[u] = a; pf[u] = b; po[u] = d; pg[u] = e;
        }

        float s_lin = blj;
#pragma unroll
        for (int u = 0; u < U; ++u) {
            float it = fast_sigmoid(pi[u]);
            float ft = fast_sigmoid(pf[u]);
            float ot = fast_sigmoid(po[u]);
            float gt = fast_sigmoid(pg[u]);   // reference: sigmoid here too
            c[u] = fmaf(ft, c[u], it * gt);
            h[u] = ot * fast_sigmoid(c[u]);   // reference: sigmoid, not tanh
            s_lin = fmaf(lin[u], h[u], s_lin);
        }

        x = fast_tanh(s_lin);
        vacc += (s == 0) ? 2.0f * x : x;      // scan double-counts out1
    }

    g_vels[j] = vacc;
}

// 4 pixels / thread: 12 front-batched LDG.128 (evict-first) + 2 STG.128
__global__ void __launch_bounds__(256) apply_kernel(
    const float4* __restrict__ lsx,
    const float4* __restrict__ lsy,
    float4* __restrict__ out,
    int nquads)
{
    int t = blockIdx.x * blockDim.x + threadIdx.x;
    if (t >= nquads) return;

    const float4* px = lsx + 6 * (size_t)t;
    const float4* py = lsy + 6 * (size_t)t;

    float4 x0 = __ldcs(px + 0), x1 = __ldcs(px + 1), x2 = __ldcs(px + 2);
    float4 x3 = __ldcs(px + 3), x4 = __ldcs(px + 4), x5 = __ldcs(px + 5);
    float4 y0 = __ldcs(py + 0), y1 = __ldcs(py + 1), y2 = __ldcs(py + 2);
    float4 y3 = __ldcs(py + 3), y4 = __ldcs(py + 4), y5 = __ldcs(py + 5);

    float v0 = g_vels[0], v1 = g_vels[1], v2 = g_vels[2];
    float v3 = g_vels[3], v4 = g_vels[4], v5 = g_vels[5];

    // pixel layout within 6 float4 (24 floats): p0=[0..5] p1=[6..11] p2=[12..17] p3=[18..23]
    float fx0 = fmaf(x0.x,v0, fmaf(x0.y,v1, fmaf(x0.z,v2, fmaf(x0.w,v3, fmaf(x1.x,v4, x1.y*v5)))));
    float fx1 = fmaf(x1.z,v0, fmaf(x1.w,v1, fmaf(x2.x,v2, fmaf(x2.y,v3, fmaf(x2.z,v4, x2.w*v5)))));
    float fx2 = fmaf(x3.x,v0, fmaf(x3.y,v1, fmaf(x3.z,v2, fmaf(x3.w,v3, fmaf(x4.x,v4, x4.y*v5)))));
    float fx3 = fmaf(x4.z,v0, fmaf(x4.w,v1, fmaf(x5.x,v2, fmaf(x5.y,v3, fmaf(x5.z,v4, x5.w*v5)))));

    float fy0 = fmaf(y0.x,v0, fmaf(y0.y,v1, fmaf(y0.z,v2, fmaf(y0.w,v3, fmaf(y1.x,v4, y1.y*v5)))));
    float fy1 = fmaf(y1.z,v0, fmaf(y1.w,v1, fmaf(y2.x,v2, fmaf(y2.y,v3, fmaf(y2.z,v4, y2.w*v5)))));
    float fy2 = fmaf(y3.x,v0, fmaf(y3.y,v1, fmaf(y3.z,v2, fmaf(y3.w,v3, fmaf(y4.x,v4, y4.y*v5)))));
    float fy3 = fmaf(y4.z,v0, fmaf(y4.w,v1, fmaf(y5.x,v2, fmaf(y5.y,v3, fmaf(y5.z,v4, y5.w*v5)))));

    __stcs(out + 2 * (size_t)t,     make_float4(fx0, fy0, fx1, fy1));
    __stcs(out + 2 * (size_t)t + 1, make_float4(fx2, fy2, fx3, fy3));
}

extern "C" void kernel_launch(void* const* d_in, const int* in_sizes, int n_in,
                              void* d_out, int out_size)
{
    const float* vel = (const float*)d_in[0];
    const float* Lsx = (const float*)d_in[1];
    const float* Lsy = (const float*)d_in[2];
    const float* Wix = (const float*)d_in[3];
    const float* Wih = (const float*)d_in[4];
    const float* bi  = (const float*)d_in[5];
    const float* Wfx = (const float*)d_in[6];
    const float* Wfh = (const float*)d_in[7];
    const float* bf  = (const float*)d_in[8];
    const float* Wox = (const float*)d_in[9];
    const float* Woh = (const float*)d_in[10];
    const float* bo  = (const float*)d_in[11];
    const float* Wgx = (const float*)d_in[12];
    const float* Wgh = (const float*)d_in[13];
    const float* bg  = (const float*)d_in[14];
    const float* linear = (const float*)d_in[15];
    const float* bl  = (const float*)d_in[16];
    const float* h0  = (const float*)d_in[17];
    const float* c0  = (const float*)d_in[18];

    int N = in_sizes[1] / V;       // pixels (1920*1080, divisible by 4)
    int nquads = N / 4;

    recurrence_kernel<<<1, 32>>>(vel, Wix, Wih, bi, Wfx, Wfh, bf,
                                 Wox, Woh, bo, Wgx, Wgh, bg,
                                 linear, bl, h0, c0);

    apply_kernel<<<(nquads + 255) / 256, 256>>>(
        (const float4*)Lsx, (const float4*)Lsy, (float4*)d_out, nquads);
}

// round 4
// speedup vs baseline: 1.0033x; 1.0033x over previous
#include <cuda_runtime.h>

#define V 6
#define U 4
#define NSTATE (V*U)   // 24
#define STEPS 63       // 64th step's output is discarded by the reference

__device__ float g_vels[8];
__device__ int   g_flag = 0;
__device__ int   g_done = 0;

__device__ __forceinline__ float fast_sigmoid(float x) {
    return __fdividef(1.0f, 1.0f + __expf(-x));
}
__device__ __forceinline__ float fast_tanh(float x) {
    return 1.0f - __fdividef(2.0f, __expf(2.0f * x) + 1.0f);
}

__global__ void __launch_bounds__(256, 4) fused_kernel(
    const float4* __restrict__ lsx,
    const float4* __restrict__ lsy,
    float4* __restrict__ out,
    int npairs,
    const float* __restrict__ vel,
    const float* __restrict__ Wix, const float* __restrict__ Wih, const float* __restrict__ bi,
    const float* __restrict__ Wfx, const float* __restrict__ Wfh, const float* __restrict__ bf,
    const float* __restrict__ Wox, const float* __restrict__ Woh, const float* __restrict__ bo,
    const float* __restrict__ Wgx, const float* __restrict__ Wgh, const float* __restrict__ bg,
    const float* __restrict__ linear, const float* __restrict__ bl,
    const float* __restrict__ h0, const float* __restrict__ c0)
{
    const unsigned FULL = 0xFFFFFFFFu;
    const int tid = threadIdx.x;
    const long long g  = (long long)blockIdx.x * blockDim.x + tid;
    const long long T  = (long long)gridDim.x * blockDim.x;
    const long long nw = T - 32;            // worker threads (block0/warp0 excluded)
    const bool isRec = (blockIdx.x == 0 && tid < 32);

    float4 x0, x1, x2, y0, y1, y2;
    long long w = g - 32;                   // worker pair index (>= 0 for all workers)
    bool have = (!isRec) && (w < npairs);

    if (isRec) {
        // ===== recurrence: lane-per-(j,u), 6 shuffles/step, 12 MUFU/step (R1-proven) =====
        int lane = tid & 31;
        int t = (lane < NSTATE) ? lane : 0;
        int j = t >> 2;
        int base = j << 2;

        float wix = Wix[t], wfx = Wfx[t], wox = Wox[t], wgx = Wgx[t];
        float bii = bi[t],  bff = bf[t],  boo = bo[t],  bgg = bg[t];
        float wih[4], wfh[4], woh[4], wgh[4];
#pragma unroll
        for (int k = 0; k < 4; ++k) {
            wih[k] = Wih[t * 4 + k];
            wfh[k] = Wfh[t * 4 + k];
            woh[k] = Woh[t * 4 + k];
            wgh[k] = Wgh[t * 4 + k];
        }
        float lin = linear[t];
        float blj = bl[j];
        float h = h0[t];
        float c = c0[t];
        float x = vel[j];
        float vacc = 0.0f;

#pragma unroll 1
        for (int s = 0; s < STEPS; ++s) {
            float ha = __shfl_sync(FULL, h, base + 0);
            float hb = __shfl_sync(FULL, h, base + 1);
            float hc = __shfl_sync(FULL, h, base + 2);
            float hd = __shfl_sync(FULL, h, base + 3);

            float pi = fmaf(wih[0], ha, bii); pi = fmaf(wih[1], hb, pi);
            pi = fmaf(wih[2], hc, pi);        pi = fmaf(wih[3], hd, pi);
            float pf = fmaf(wfh[0], ha, bff); pf = fmaf(wfh[1], hb, pf);
            pf = fmaf(wfh[2], hc, pf);        pf = fmaf(wfh[3], hd, pf);
            float po = fmaf(woh[0], ha, boo); po = fmaf(woh[1], hb, po);
            po = fmaf(woh[2], hc, po);        po = fmaf(woh[3], hd, po);
            float pg = fmaf(wgh[0], ha, bgg); pg = fmaf(wgh[1], hb, pg);
            pg = fmaf(wgh[2], hc, pg);        pg = fmaf(wgh[3], hd, pg);

            pi = fmaf(wix, x, pi);
            pf = fmaf(wfx, x, pf);
            po = fmaf(wox, x, po);
            pg = fmaf(wgx, x, pg);

            float it = fast_sigmoid(pi);
            float ft = fast_sigmoid(pf);
            float ot = fast_sigmoid(po);
            float gt = fast_sigmoid(pg);     // reference: sigmoid here too

            c = fmaf(ft, c, it * gt);
            h = ot * fast_sigmoid(c);        // reference: sigmoid, not tanh

            float ssum = lin * h;
            ssum += __shfl_xor_sync(FULL, ssum, 1);
            ssum += __shfl_xor_sync(FULL, ssum, 2);
            x = fast_tanh(ssum + blj);

            vacc += (s == 0) ? 2.0f * x : x; // scan double-counts out1
        }

        if (lane < NSTATE && (t & 3) == 0) g_vels[j] = vacc;
        __threadfence();
        if (lane == 0) atomicExch(&g_flag, 1);
    } else {
        // ===== workers: issue first-iteration loads (3 float4 per array per pair) =====
        if (have) {
            const float4* px = lsx + 3 * w;
            const float4* py = lsy + 3 * w;
            x0 = px[0]; x1 = px[1]; x2 = px[2];
            y0 = py[0]; y1 = py[1]; y2 = py[2];
        }
        // ===== then prefetch both arrays into L2 (independent of vels) =====
        // 128B lines; descending order so earliest-needed lines are freshest in L2
        const long long nlines = ((long long)npairs * 48) >> 7;  // bytes per array / 128
        const char* bx = (const char*)lsx;
        const char* by = (const char*)lsy;
        for (long long l = nlines - 1 - g; l >= 0; l -= T) {
            const char* ax = bx + (l << 7);
            const char* ay = by + (l << 7);
            asm volatile("prefetch.global.L2 [%0];" :: "l"(ax));
            asm volatile("prefetch.global.L2 [%0];" :: "l"(ay));
        }
    }

    // ===== wait for vels (1 poller per block) =====
    if (tid == 0) {
        while (atomicAdd(&g_flag, 0) == 0) __nanosleep(128);
    }
    __syncthreads();

    const float v0 = __ldcg(&g_vels[0]), v1 = __ldcg(&g_vels[1]), v2 = __ldcg(&g_vels[2]);
    const float v3 = __ldcg(&g_vels[3]), v4 = __ldcg(&g_vels[4]), v5 = __ldcg(&g_vels[5]);

    // ===== worker loop: 2 pixels per iteration (R1-proven access shape) =====
    while (have) {
        float fx0 = fmaf(x0.x,v0, fmaf(x0.y,v1, fmaf(x0.z,v2, fmaf(x0.w,v3, fmaf(x1.x,v4, x1.y*v5)))));
        float fx1 = fmaf(x1.z,v0, fmaf(x1.w,v1, fmaf(x2.x,v2, fmaf(x2.y,v3, fmaf(x2.z,v4, x2.w*v5)))));
        float fy0 = fmaf(y0.x,v0, fmaf(y0.y,v1, fmaf(y0.z,v2, fmaf(y0.w,v3, fmaf(y1.x,v4, y1.y*v5)))));
        float fy1 = fmaf(y1.z,v0, fmaf(y1.w,v1, fmaf(y2.x,v2, fmaf(y2.y,v3, fmaf(y2.z,v4, y2.w*v5)))));
        __stcs(out + w, make_float4(fx0, fy0, fx1, fy1));

        w += nw;
        have = (w < npairs);
        if (have) {
            const float4* px = lsx + 3 * w;
            const float4* py = lsy + 3 * w;
            x0 = px[0]; x1 = px[1]; x2 = px[2];
            y0 = py[0]; y1 = py[1]; y2 = py[2];
        }
    }

    // ===== reset flag so every graph replay re-waits (determinism) =====
    __syncthreads();
    if (tid == 0) {
        int d = atomicAdd(&g_done, 1) + 1;
        if (d == (int)gridDim.x) {
            atomicExch(&g_done, 0);
            __threadfence();
            atomicExch(&g_flag, 0);
        }
    }
}

extern "C" void kernel_launch(void* const* d_in, const int* in_sizes, int n_in,
                              void* d_out, int out_size)
{
    const float* vel = (const float*)d_in[0];
    const float* Lsx = (const float*)d_in[1];
    const float* Lsy = (const float*)d_in[2];
    const float* Wix = (const float*)d_in[3];
    const float* Wih = (const float*)d_in[4];
    const float* bi  = (const float*)d_in[5];
    const float* Wfx = (const float*)d_in[6];
    const float* Wfh = (const float*)d_in[7];
    const float* bf  = (const float*)d_in[8];
    const float* Wox = (const float*)d_in[9];
    const float* Woh = (const float*)d_in[10];
    const float* bo  = (const float*)d_in[11];
    const float* Wgx = (const float*)d_in[12];
    const float* Wgh = (const float*)d_in[13];
    const float* bg  = (const float*)d_in[14];
    const float* linear = (const float*)d_in[15];
    const float* bl  = (const float*)d_in[16];
    const float* h0  = (const float*)d_in[17];
    const float* c0  = (const float*)d_in[18];

    int N = in_sizes[1] / V;       // pixels
    int npairs = N / 2;            // 2 pixels per thread-iteration

    int blocks = 592;              // ~4/SM; only block 0 must run early (wave 1)
    fused_kernel<<<blocks, 256>>>(
        (const float4*)Lsx, (const float4*)Lsy, (float4*)d_out, npairs,
        vel, Wix, Wih, bi, Wfx, Wfh, bf, Wox, Woh, bo, Wgx, Wgh, bg,
        linear, bl, h0, c0);
}